// round 2
// baseline (speedup 1.0000x reference)
#include <cuda_runtime.h>
#include <math.h>

// Problem constants
#define Bn 32
#define CIN 96
#define Tt 288
#define Vv 25
#define Ss 3
#define Cc 96
#define VP 28          // padded V for z scratch
#define TTc 32         // t's per CTA (pass 1)
#define NT 9           // 288/32
#define HC 48          // c's per CTA half
#define Jn 144         // Ss*HC outputs per CTA
#define JR 148         // row stride sWt/sYt (mult of 4)
#define XR 56          // duplicated-x row stride
#define AR 56          // duplicated-A row stride

typedef unsigned long long ull;

__device__ float  g_z[(size_t)Bn * Cc * Tt * VP];
__device__ double g_psum[Cc * Bn];
__device__ double g_pss [Cc * Bn];
__device__ float  g_mean[Cc];
__device__ float  g_rstd[Cc];

__device__ __forceinline__ void fma2(ull &d, ull a, ull b) {
    asm("fma.rn.f32x2 %0, %1, %2, %0;" : "+l"(d) : "l"(a), "l"(b));
}
__device__ __forceinline__ float lo2(ull v) { return __uint_as_float((unsigned)(v & 0xffffffffull)); }
__device__ __forceinline__ float hi2(ull v) { return __uint_as_float((unsigned)(v >> 32)); }

// ---------------------------------------------------------------------------
// Pass 1: per (b, t-tile, c-half):
//   y[j][v] = sum_k W[o(j)][k] * x[b,k,t,v] + bias    (j = s*48+cc, o = s*96+h*48+cc)
//   z[c][m] = sum_{s,n} y[s*48+cc][n] * A[s][n][m]
// smem (floats):
//   sWt [96][148]  sWt[k][j]=W[o(j)][k]                    14208
//   sYt [28][148]  sYt[v][j]=y[j][v]                        4144
//   sXd [96][56]   duplicated x slice: (x,x) pairs          5376
//   sAd [3][25][56] duplicated A (pad m 25..27 = 0)         4200
//   sB  [144]                                                144
//   total 28072 floats = 112288 B  ->  2 CTAs/SM
// ---------------------------------------------------------------------------
__global__ void __launch_bounds__(256, 2)
pass1_kernel(const float* __restrict__ x, const float* __restrict__ A,
             const float* __restrict__ W, const float* __restrict__ bias) {
    extern __shared__ float smem[];
    float* sWt = smem;              // 14208
    float* sYt = smem + 14208;      //  4144
    float* sXd = smem + 18352;      //  5376
    float* sAd = smem + 23728;      //  4200
    float* sB  = smem + 27928;      //   144

    const int tid = threadIdx.x;
    const int t0  = blockIdx.x * TTc;
    const int b   = blockIdx.y;
    const int h   = blockIdx.z;

    // ---- preamble: weights (transposed, half), A duplicated, bias, x(t0) ----
    for (int idx = tid; idx < Jn * CIN; idx += 256) {
        int j = idx / CIN, k = idx % CIN;
        int s = j / HC, cc = j % HC;
        sWt[k * JR + j] = W[(s * Cc + h * HC + cc) * CIN + k];
    }
    for (int idx = tid; idx < Ss * Vv * VP; idx += 256) {
        int s = idx / (Vv * VP);
        int r = idx % (Vv * VP);
        int n = r / VP, m = r % VP;
        float a = (m < Vv) ? A[(s * Vv + n) * Vv + m] : 0.0f;
        sAd[(s * Vv + n) * AR + 2 * m]     = a;
        sAd[(s * Vv + n) * AR + 2 * m + 1] = a;
    }
    for (int idx = tid; idx < Jn; idx += 256) {
        int s = idx / HC, cc = idx % HC;
        sB[idx] = bias[s * Cc + h * HC + cc];
    }
    // zero-pad x dup columns m=25..27
    for (int idx = tid; idx < CIN * (VP - Vv); idx += 256) {
        int i = idx / (VP - Vv), p = idx % (VP - Vv);
        sXd[i * XR + 2 * (Vv + p)]     = 0.0f;
        sXd[i * XR + 2 * (Vv + p) + 1] = 0.0f;
    }
    // precompute per-thread x prefetch addressing (fixed across t)
    int  boff[10]; int soff[10]; bool pvld[10];
    for (int r = 0; r < 10; r++) {
        int idx = tid + r * 256;
        pvld[r] = idx < CIN * Vv;
        int i = idx / Vv, n = idx % Vv;
        boff[r] = ((b * CIN + i) * Tt) * Vv + n;
        soff[r] = i * XR + 2 * n;
    }
    // initial x(t0)
    for (int r = 0; r < 10; r++) {
        if (pvld[r]) {
            float v = x[boff[r] + t0 * Vv];
            sXd[soff[r]] = v; sXd[soff[r] + 1] = v;
        }
    }
    __syncthreads();

    // BIG mapping: 126 threads, jb = tid/7 (0..17) -> 8 j's, mt = tid%7 -> 4 m's
    const int mtB = tid % 7;
    const int jbB = tid / 7;
    // SMALL mapping: 84 threads, cb = tid/7 (0..11) -> 4 c's, mt = tid%7 -> 4 m's
    const int mtS = tid % 7;
    const int cbS = tid / 7;

    for (int tt = 0; tt < TTc; tt++) {
        const int t = t0 + tt;
        const bool hn = (tt + 1 < TTc);

        // issue prefetch loads early
        float pf[10];
        if (hn) {
#pragma unroll
            for (int r = 0; r < 10; r++)
                if (pvld[r]) pf[r] = x[boff[r] + (t + 1) * Vv];
        }

        // ---- BIG: y = W^T x (+bias), f32x2 over j-pairs ----
        if (tid < 126) {
            const int j0 = jbB * 8;
            const int m0 = mtB * 4;
            ull acc[4][4];
#pragma unroll
            for (int p = 0; p < 4; p++)
#pragma unroll
                for (int q = 0; q < 4; q++) acc[p][q] = 0ull;

            const float* wp = sWt + j0;
            const float* xp = sXd + 2 * m0;
#pragma unroll 4
            for (int k = 0; k < CIN; k++) {
                ulonglong2 w01 = *(const ulonglong2*)(wp);
                ulonglong2 w23 = *(const ulonglong2*)(wp + 4);
                ulonglong2 x01 = *(const ulonglong2*)(xp);
                ulonglong2 x23 = *(const ulonglong2*)(xp + 4);
                fma2(acc[0][0], w01.x, x01.x); fma2(acc[0][1], w01.x, x01.y);
                fma2(acc[0][2], w01.x, x23.x); fma2(acc[0][3], w01.x, x23.y);
                fma2(acc[1][0], w01.y, x01.x); fma2(acc[1][1], w01.y, x01.y);
                fma2(acc[1][2], w01.y, x23.x); fma2(acc[1][3], w01.y, x23.y);
                fma2(acc[2][0], w23.x, x01.x); fma2(acc[2][1], w23.x, x01.y);
                fma2(acc[2][2], w23.x, x23.x); fma2(acc[2][3], w23.x, x23.y);
                fma2(acc[3][0], w23.y, x01.x); fma2(acc[3][1], w23.y, x01.y);
                fma2(acc[3][2], w23.y, x23.x); fma2(acc[3][3], w23.y, x23.y);
                wp += JR;
                xp += XR;
            }
            // epilogue: +bias, store transposed
            float b0 = sB[j0],     b1 = sB[j0 + 1], b2 = sB[j0 + 2], b3 = sB[j0 + 3];
            float b4 = sB[j0 + 4], b5 = sB[j0 + 5], b6 = sB[j0 + 6], b7 = sB[j0 + 7];
#pragma unroll
            for (int q = 0; q < 4; q++) {
                float4 v0, v1;
                v0.x = lo2(acc[0][q]) + b0; v0.y = hi2(acc[0][q]) + b1;
                v0.z = lo2(acc[1][q]) + b2; v0.w = hi2(acc[1][q]) + b3;
                v1.x = lo2(acc[2][q]) + b4; v1.y = hi2(acc[2][q]) + b5;
                v1.z = lo2(acc[3][q]) + b6; v1.w = hi2(acc[3][q]) + b7;
                *(float4*)(sYt + (m0 + q) * JR + j0)     = v0;
                *(float4*)(sYt + (m0 + q) * JR + j0 + 4) = v1;
            }
        }
        __syncthreads();   // sYt ready, sXd free

        // store prefetched x (duplicated)
        if (hn) {
#pragma unroll
            for (int r = 0; r < 10; r++)
                if (pvld[r]) { sXd[soff[r]] = pf[r]; sXd[soff[r] + 1] = pf[r]; }
        }

        // ---- SMALL: z[c][m] = sum_{s,n} y * A, f32x2 over c-pairs ----
        if (tid < 84) {
            const int c0 = cbS * 4;
            const int m0 = mtS * 4;
            ull acc[2][4];
#pragma unroll
            for (int p = 0; p < 2; p++)
#pragma unroll
                for (int q = 0; q < 4; q++) acc[p][q] = 0ull;
#pragma unroll
            for (int s = 0; s < Ss; s++) {
                const float* yrow = sYt + s * HC + c0;
                const float* arow = sAd + s * (Vv * AR) + 2 * m0;
#pragma unroll 5
                for (int n = 0; n < Vv; n++) {
                    ulonglong2 yy  = *(const ulonglong2*)(yrow + n * JR);
                    ulonglong2 a01 = *(const ulonglong2*)(arow + n * AR);
                    ulonglong2 a23 = *(const ulonglong2*)(arow + n * AR + 4);
                    fma2(acc[0][0], yy.x, a01.x); fma2(acc[0][1], yy.x, a01.y);
                    fma2(acc[0][2], yy.x, a23.x); fma2(acc[0][3], yy.x, a23.y);
                    fma2(acc[1][0], yy.y, a01.x); fma2(acc[1][1], yy.y, a01.y);
                    fma2(acc[1][2], yy.y, a23.x); fma2(acc[1][3], yy.y, a23.y);
                }
            }
            // store z: 4 channels x 4 m (STG.128 each)
            const int cglob = h * HC + c0;
            const size_t cstride = (size_t)Tt * VP;
            float* zb = g_z + ((size_t)(b * Cc + cglob) * Tt + t) * VP + m0;
            float4 v;
            v.x = lo2(acc[0][0]); v.y = lo2(acc[0][1]); v.z = lo2(acc[0][2]); v.w = lo2(acc[0][3]);
            *(float4*)(zb) = v;
            v.x = hi2(acc[0][0]); v.y = hi2(acc[0][1]); v.z = hi2(acc[0][2]); v.w = hi2(acc[0][3]);
            *(float4*)(zb + cstride) = v;
            v.x = lo2(acc[1][0]); v.y = lo2(acc[1][1]); v.z = lo2(acc[1][2]); v.w = lo2(acc[1][3]);
            *(float4*)(zb + 2 * cstride) = v;
            v.x = hi2(acc[1][0]); v.y = hi2(acc[1][1]); v.z = hi2(acc[1][2]); v.w = hi2(acc[1][3]);
            *(float4*)(zb + 3 * cstride) = v;
        }
        __syncthreads();   // sYt consumed, sXd written
    }
}

// ---------------------------------------------------------------------------
// Pass 2a: per-(c,b) plane partial BN stats over windowed z.
// ---------------------------------------------------------------------------
__global__ void __launch_bounds__(256)
pass2a_kernel() {
    const int c = blockIdx.x;
    const int b = blockIdx.y;
    const int tid = threadIdx.x;
    __shared__ float sP[Tt * VP];
    __shared__ double red[512];

    const float* src = g_z + (size_t)(b * Cc + c) * Tt * VP;
    for (int i = tid; i < Tt * VP; i += 256) sP[i] = src[i];
    __syncthreads();

    double s = 0.0, q = 0.0;
    for (int i = tid; i < Tt * Vv; i += 256) {
        int t = i / Vv, m = i % Vv;
        float v = 0.0f;
#pragma unroll
        for (int k = -2; k <= 2; k++) {
            int tk = t + k;
            if (tk >= 0 && tk < Tt) v += sP[tk * VP + m];
        }
        v *= 0.2f;
        s += (double)v;
        q += (double)v * (double)v;
    }
    red[tid] = s; red[256 + tid] = q;
    __syncthreads();
    for (int s2 = 128; s2 > 0; s2 >>= 1) {
        if (tid < s2) {
            red[tid] += red[tid + s2];
            red[256 + tid] += red[256 + tid + s2];
        }
        __syncthreads();
    }
    if (tid == 0) {
        g_psum[c * Bn + b] = red[0];
        g_pss [c * Bn + b] = red[256];
    }
}

// ---------------------------------------------------------------------------
// Pass 2b: reduce 32 partials per channel -> mean/rstd
// ---------------------------------------------------------------------------
__global__ void __launch_bounds__(32)
pass2b_kernel() {
    const int c = blockIdx.x;
    const int lane = threadIdx.x;
    double s = g_psum[c * Bn + lane];
    double q = g_pss [c * Bn + lane];
#pragma unroll
    for (int o = 16; o > 0; o >>= 1) {
        s += __shfl_down_sync(0xffffffffu, s, o);
        q += __shfl_down_sync(0xffffffffu, q, o);
    }
    if (lane == 0) {
        const double N = (double)Bn * Tt * Vv;
        double mean = s / N;
        double var  = q / N - mean * mean;
        g_mean[c] = (float)mean;
        g_rstd[c] = (float)(1.0 / sqrt(var + 1e-5));
    }
}

// ---------------------------------------------------------------------------
// Pass 3: window-avg + normalize + affine + relu
// ---------------------------------------------------------------------------
__global__ void __launch_bounds__(256)
pass3_kernel(const float* __restrict__ gamma, const float* __restrict__ beta,
             float* __restrict__ out) {
    const int c = blockIdx.x;
    const int b = blockIdx.y;
    const int tid = threadIdx.x;
    __shared__ float sP[Tt * VP];

    const float* src = g_z + (size_t)(b * Cc + c) * Tt * VP;
    for (int i = tid; i < Tt * VP; i += 256) sP[i] = src[i];
    __syncthreads();

    const float mean = g_mean[c];
    const float rstd = g_rstd[c];
    const float sc = rstd * gamma[c];
    const float sh = beta[c] - mean * sc;

    float* dst = out + (size_t)(b * Cc + c) * Tt * Vv;
    for (int i = tid; i < Tt * Vv; i += 256) {
        int t = i / Vv, m = i % Vv;
        float v = 0.0f;
#pragma unroll
        for (int k = -2; k <= 2; k++) {
            int tk = t + k;
            if (tk >= 0 && tk < Tt) v += sP[tk * VP + m];
        }
        v *= 0.2f;
        float o = fmaf(v, sc, sh);
        dst[i] = fmaxf(o, 0.0f);
    }
}

// ---------------------------------------------------------------------------
extern "C" void kernel_launch(void* const* d_in, const int* in_sizes, int n_in,
                              void* d_out, int out_size) {
    const float* x     = (const float*)d_in[0];
    const float* A     = (const float*)d_in[1];
    const float* W     = (const float*)d_in[2];
    const float* bias  = (const float*)d_in[3];
    const float* gamma = (const float*)d_in[4];
    const float* beta  = (const float*)d_in[5];
    float* out = (float*)d_out;

    const int smem1 = 28072 * 4;   // 112288 bytes
    cudaFuncSetAttribute(pass1_kernel, cudaFuncAttributeMaxDynamicSharedMemorySize, smem1);

    pass1_kernel<<<dim3(NT, Bn, 2), 256, smem1>>>(x, A, W, bias);
    pass2a_kernel<<<dim3(Cc, Bn), 256>>>();
    pass2b_kernel<<<Cc, 32>>>();
    pass3_kernel<<<dim3(Cc, Bn), 256>>>(gamma, beta, out);
}